// round 10
// baseline (speedup 1.0000x reference)
#include <cuda_runtime.h>

// Problem constants
#define NB    32
#define NH    64
#define NW    64
#define NT    100
#define COUT  8
#define KS    6
#define LP    2

// Tiling
#define TILE_W 16
#define TILE_H 8
#define HALO_W (TILE_W + KS - 1)   // 21
#define HALO_H (TILE_H + KS - 1)   // 13
#define NPIX   (HALO_W * HALO_H)   // 273
#define NTHR   256                 // 16 x 8 x 2 (cout split)
#define CPT    4                   // couts per thread
#define NCH    13                  // chunks 0..11: 8 timesteps, chunk 12: 4 (t=96..99)
#define NHWT   (NH * NW * NT)      // 409600
#define PSTRIDE 6                  // u64 per pixel (48B): 16B-aligned -> cp16 + LDS.128,
                                   // 8-pixel bank cycle covers all 32 banks (conflict-free)
#define NBUF   3                   // triple buffer, prefetch distance 2, 1 sync per chunk

typedef unsigned long long u64;

__device__ __forceinline__ void upk2(u64 v, float& lo, float& hi) {
    asm("mov.b64 {%0, %1}, %2;" : "=f"(lo), "=f"(hi) : "l"(v));
}
__device__ __forceinline__ u64 fma2(u64 a, u64 b, u64 c) {
    u64 d; asm("fma.rn.f32x2 %0, %1, %2, %3;" : "=l"(d) : "l"(a), "l"(b), "l"(c)); return d;
}
__device__ __forceinline__ unsigned smem_u32(const void* p) {
    return (unsigned)__cvta_generic_to_shared(p);
}
__device__ __forceinline__ void cp16(unsigned dst, const void* src) {
    asm volatile("cp.async.ca.shared.global [%0], [%1], 16;" :: "r"(dst), "l"(src));
}
__device__ __forceinline__ void cp_commit() { asm volatile("cp.async.commit_group;" ::: "memory"); }
__device__ __forceinline__ void cp_wait1()  { asm volatile("cp.async.wait_group 1;" ::: "memory"); }
__device__ __forceinline__ void cp_wait0()  { asm volatile("cp.async.wait_group 0;" ::: "memory"); }

// exact reference recurrence step: ut = (ut - st_prev*thr) + wx ; st = (ut > 0)
__device__ __forceinline__ float stepf(float& u, float wx, float thr) {
    u = (u - (u > 0.f ? thr : 0.f)) + wx;
    return (u > 0.f) ? 1.f : 0.f;
}

__global__ __launch_bounds__(NTHR, 3)   // ~85 regs budget; 24 warps/SM
void sconv_spike_kernel(const float* __restrict__ x,
                        const float* __restrict__ w,
                        const float* __restrict__ thr_p,
                        float* __restrict__ out)
{
    // triple-buffered input tile, 48B pixel stride (16B-aligned, conflict-free)
    __shared__ __align__(16) u64 sx[NBUF][NPIX * PSTRIDE];
    // weights tap-major: sw2[tap*8 + cout], each duplicated (w,w) for f32x2
    __shared__ __align__(16) u64 sw2[KS * KS * COUT];

    const int tx  = threadIdx.x;
    const int ty  = threadIdx.y;
    const int cz  = threadIdx.z;          // cout half: couts [cz*4, cz*4+4)
    const int tid = tx + TILE_W * ty + (TILE_W * TILE_H) * cz;
    const int b   = blockIdx.z;
    const int h0  = blockIdx.y * TILE_H;
    const int w0  = blockIdx.x * TILE_W;

    // weights: transpose [cout][tap] -> [tap][cout], duplicate into both lanes
    for (int i = tid; i < KS * KS * COUT; i += NTHR) {
        int tap = i >> 3, c = i & 7;
        unsigned bits = __float_as_uint(w[c * (KS * KS) + tap]);
        sw2[i] = ((u64)bits << 32) | (u64)bits;
    }
    // zero OOB halo pixels in all buffers once (never written by cp16)
    for (int pix = tid; pix < NPIX; pix += NTHR) {
        int r = pix / HALO_W, c = pix % HALO_W;
        int gh = h0 - LP + r, gw = w0 - LP + c;
        if (gh < 0 || gh >= NH || gw < 0 || gw >= NW) {
#pragma unroll
            for (int bb = 0; bb < NBUF; bb++)
#pragma unroll
                for (int j = 0; j < 4; j++)
                    sx[bb][pix * PSTRIDE + j] = 0ull;
        }
    }
    const float thr = thr_p[0];

    const float* xb = x + (size_t)b * NH * NW * NT;
    const int h  = h0 + ty;
    const int wq = w0 + tx;
    const int cbase = cz * CPT;
    float* obase = out + (size_t)b * COUT * NHWT
                       + ((size_t)h * NW + wq) * NT
                       + (size_t)cbase * NHWT;

    float ut[CPT];
#pragma unroll
    for (int c = 0; c < CPT; c++) ut[c] = 0.f;

    // chunk loader: chunk k -> t0 = 8k; full chunks: 2 cp16/pixel, tail: 1
    auto load_chunk = [&](int k) {
        int buf = k % NBUF;
        int t0  = k * 8;
        int n16 = (k == NCH - 1) ? 1 : 2;
        int total = NPIX * n16;
        for (int idx = tid; idx < total; idx += NTHR) {
            int pix, j;
            if (n16 == 2) { pix = idx >> 1; j = idx & 1; }
            else          { pix = idx;      j = 0; }
            int r = pix / HALO_W, c = pix % HALO_W;
            int gh = h0 - LP + r, gw = w0 - LP + c;
            if (gh >= 0 && gh < NH && gw >= 0 && gw < NW) {
                const float* src = xb + ((size_t)gh * NW + gw) * NT + t0 + j * 4;
                cp16(smem_u32(&sx[buf][pix * PSTRIDE + j * 2]), src);
            }
        }
        cp_commit();
    };

    load_chunk(0);
    load_chunk(1);

#pragma unroll 1
    for (int i = 0; i < NCH; i++) {
        // outstanding cp.async groups at this point: {i, i+1}∩range
        if (i + 1 < NCH) cp_wait1();   // group i retired
        else             cp_wait0();
        __syncthreads();               // chunk i visible; iter i-1 reads all done

        const int buf = i % NBUF;
        const int t0  = i * 8;
        const bool full = (i != NCH - 1);

        u64 a0[CPT], a1[CPT], a2[CPT], a3[CPT];
#pragma unroll
        for (int c = 0; c < CPT; c++) { a0[c] = 0; a1[c] = 0; a2[c] = 0; a3[c] = 0; }

        if (full) {
            // tap loop with one-tap x prefetch, x as 2 x LDS.128
            const ulonglong2* xp =
                (const ulonglong2*)&sx[buf][(ty * HALO_W + tx) * PSTRIDE];
            ulonglong2 xA = xp[0], xB = xp[1];
#pragma unroll
            for (int tap = 0; tap < KS * KS; tap++) {
                ulonglong2 nA, nB;
                if (tap + 1 < KS * KS) {
                    const int nkh = (tap + 1) / KS, nkw = (tap + 1) % KS;
                    const ulonglong2* np = (const ulonglong2*)
                        &sx[buf][((ty + nkh) * HALO_W + (tx + nkw)) * PSTRIDE];
                    nA = np[0]; nB = np[1];
                }
                ulonglong2 wA = *(const ulonglong2*)&sw2[tap * COUT + cbase];
                ulonglong2 wB = *(const ulonglong2*)&sw2[tap * COUT + cbase + 2];
                a0[0] = fma2(xA.x, wA.x, a0[0]); a1[0] = fma2(xA.y, wA.x, a1[0]);
                a2[0] = fma2(xB.x, wA.x, a2[0]); a3[0] = fma2(xB.y, wA.x, a3[0]);
                a0[1] = fma2(xA.x, wA.y, a0[1]); a1[1] = fma2(xA.y, wA.y, a1[1]);
                a2[1] = fma2(xB.x, wA.y, a2[1]); a3[1] = fma2(xB.y, wA.y, a3[1]);
                a0[2] = fma2(xA.x, wB.x, a0[2]); a1[2] = fma2(xA.y, wB.x, a1[2]);
                a2[2] = fma2(xB.x, wB.x, a2[2]); a3[2] = fma2(xB.y, wB.x, a3[2]);
                a0[3] = fma2(xA.x, wB.y, a0[3]); a1[3] = fma2(xA.y, wB.y, a1[3]);
                a2[3] = fma2(xB.x, wB.y, a2[3]); a3[3] = fma2(xB.y, wB.y, a3[3]);
                if (tap + 1 < KS * KS) { xA = nA; xB = nB; }
            }

            // prefetch burst here: overlaps recurrence/stores/barrier,
            // keeps LDGSTS off the LDS-dense tap loop
            if (i + 2 < NCH) load_chunk(i + 2);

#pragma unroll
            for (int c = 0; c < CPT; c++) {
                float wx0, wx1, wx2, wx3, wx4, wx5, wx6, wx7;
                upk2(a0[c], wx0, wx1); upk2(a1[c], wx2, wx3);
                upk2(a2[c], wx4, wx5); upk2(a3[c], wx6, wx7);
                float u = ut[c];
                float s0 = stepf(u, wx0, thr), s1 = stepf(u, wx1, thr);
                float s2 = stepf(u, wx2, thr), s3 = stepf(u, wx3, thr);
                float s4 = stepf(u, wx4, thr), s5 = stepf(u, wx5, thr);
                float s6 = stepf(u, wx6, thr), s7 = stepf(u, wx7, thr);
                ut[c] = u;
                float4* p = (float4*)(obase + (size_t)c * NHWT + t0);
                p[0] = make_float4(s0, s1, s2, s3);
                p[1] = make_float4(s4, s5, s6, s7);
            }
        } else {
            // tail: t = 96..99 (one ulonglong2 per pixel)
#pragma unroll
            for (int kh = 0; kh < KS; kh++) {
#pragma unroll
                for (int kw = 0; kw < KS; kw++) {
                    const int tap = kh * KS + kw;
                    const ulonglong2* xp = (const ulonglong2*)
                        &sx[buf][((ty + kh) * HALO_W + (tx + kw)) * PSTRIDE];
                    ulonglong2 xA = xp[0];
                    ulonglong2 wA = *(const ulonglong2*)&sw2[tap * COUT + cbase];
                    ulonglong2 wB = *(const ulonglong2*)&sw2[tap * COUT + cbase + 2];
                    a0[0] = fma2(xA.x, wA.x, a0[0]); a1[0] = fma2(xA.y, wA.x, a1[0]);
                    a0[1] = fma2(xA.x, wA.y, a0[1]); a1[1] = fma2(xA.y, wA.y, a1[1]);
                    a0[2] = fma2(xA.x, wB.x, a0[2]); a1[2] = fma2(xA.y, wB.x, a1[2]);
                    a0[3] = fma2(xA.x, wB.y, a0[3]); a1[3] = fma2(xA.y, wB.y, a1[3]);
                }
            }
#pragma unroll
            for (int c = 0; c < CPT; c++) {
                float wx0, wx1, wx2, wx3;
                upk2(a0[c], wx0, wx1); upk2(a1[c], wx2, wx3);
                float u = ut[c];
                float s0 = stepf(u, wx0, thr), s1 = stepf(u, wx1, thr);
                float s2 = stepf(u, wx2, thr), s3 = stepf(u, wx3, thr);
                ut[c] = u;
                *(float4*)(obase + (size_t)c * NHWT + t0) = make_float4(s0, s1, s2, s3);
            }
        }
    }
}

extern "C" void kernel_launch(void* const* d_in, const int* in_sizes, int n_in,
                              void* d_out, int out_size)
{
    const float* x   = (const float*)d_in[0];  // [32,1,64,64,100]
    const float* w   = (const float*)d_in[1];  // [8,1,6,6]
    const float* thr = (const float*)d_in[2];  // [1]
    float* out = (float*)d_out;                // [32,8,64,64,100]

    dim3 block(TILE_W, TILE_H, 2);             // 256 threads, cout split on z
    dim3 grid(NW / TILE_W, NH / TILE_H, NB);   // (4, 8, 32)
    sconv_spike_kernel<<<grid, block>>>(x, w, thr, out);
}